// round 14
// baseline (speedup 1.0000x reference)
#include <cuda_runtime.h>
#include <cuda_bf16.h>

#define B_  8
#define H_  8
#define N_  512
#define K_  16
#define BN  (B_*N_)          // 4096
#define NN  (N_*N_)          // 262144

__device__ float g_A[BN * 256];     // per-(b,n) algebra element A, row-major 16x16
__device__ float g_V[BN * K_];      // v = exp(-A) mu

// ---------------------------------------------------------------------------
// Warp-collective: y = exp(A) x for a 16x16 A (M-term Taylor, Horner).
// Lane l owns row r = l&15 of A. x_own = component r of x (lanes 16-31 mirror).
// ---------------------------------------------------------------------------
template<int M>
__device__ __forceinline__ float exp_apply(const float Ar[16], float x_own) {
    float x[16], y[16];
    #pragma unroll
    for (int c = 0; c < 16; ++c) {
        x[c] = __shfl_sync(0xffffffffu, x_own, c);
        y[c] = x[c];
    }
    float y_own = x_own;
    #pragma unroll
    for (int k = M; k >= 1; --k) {
        float z0 = 0.0f, z1 = 0.0f;
        #pragma unroll
        for (int c = 0; c < 16; c += 2) {
            z0 += Ar[c]     * y[c];
            z1 += Ar[c + 1] * y[c + 1];
        }
        float zk = (z0 + z1) * (1.0f / (float)k);
        y_own = x_own + zk;
        #pragma unroll
        for (int c = 0; c < 16; ++c)
            y[c] = x[c] + __shfl_sync(0xffffffffu, zk, c);
    }
    return y_own;
}

__device__ __forceinline__ float4 head_sum8(const float4 h[8]) {
    float4 o;
    o.x = (((h[0].x+h[1].x)+(h[2].x+h[3].x))+((h[4].x+h[5].x)+(h[6].x+h[7].x)))*0.125f;
    o.y = (((h[0].y+h[1].y)+(h[2].y+h[3].y))+((h[4].y+h[5].y)+(h[6].y+h[7].y)))*0.125f;
    o.z = (((h[0].z+h[1].z)+(h[2].z+h[3].z))+((h[4].z+h[5].z)+(h[6].z+h[7].z)))*0.125f;
    o.w = (((h[0].w+h[1].w)+(h[2].w+h[3].w))+((h[4].w+h[5].w)+(h[6].w+h[7].w)))*0.125f;
    return o;
}

// ---------------------------------------------------------------------------
// Kernel 0: per (b,n): A = sum_g phi_g G_g (store), v = exp(-A) mu (store).
// ---------------------------------------------------------------------------
__global__ __launch_bounds__(256)
void prep_kernel(const float* __restrict__ mu,
                 const float* __restrict__ phi,
                 const float* __restrict__ gen) {
    int w = threadIdx.x >> 5, lane = threadIdx.x & 31, r = lane & 15;
    int bn = blockIdx.x * 8 + w;

    float p0 = phi[bn * 3 + 0], p1 = phi[bn * 3 + 1], p2 = phi[bn * 3 + 2];

    float Ar[16];
    const float4* g4 = (const float4*)gen;
    #pragma unroll
    for (int q = 0; q < 4; ++q) {
        float4 a = g4[(0 * 256 + r * 16) / 4 + q];
        float4 b = g4[(1 * 256 + r * 16) / 4 + q];
        float4 c = g4[(2 * 256 + r * 16) / 4 + q];
        Ar[4 * q + 0] = p0 * a.x + p1 * b.x + p2 * c.x;
        Ar[4 * q + 1] = p0 * a.y + p1 * b.y + p2 * c.y;
        Ar[4 * q + 2] = p0 * a.z + p1 * b.z + p2 * c.z;
        Ar[4 * q + 3] = p0 * a.w + p1 * b.w + p2 * c.w;
    }
    if (lane < 16) {
        float4* A4 = (float4*)(g_A + (size_t)bn * 256 + r * 16);
        #pragma unroll
        for (int q = 0; q < 4; ++q)
            A4[q] = make_float4(Ar[4*q], Ar[4*q+1], Ar[4*q+2], Ar[4*q+3]);
    }

    float nAr[16];
    #pragma unroll
    for (int c = 0; c < 16; ++c) nAr[c] = -Ar[c];

    float x_own = mu[bn * 16 + r];
    float v = exp_apply<16>(nAr, x_own);
    if (lane < 16) g_V[bn * 16 + lane] = v;
}

// ---------------------------------------------------------------------------
// Kernel 1: pipelined stream+compute. Block = 8 warps = 8 rows of one batch.
// The beta stream is chunked (4 chunks x 128 j) and double-buffered in
// WARP-PRIVATE smem rows (cbuf[2][8][128]) — so the j-loop needs only
// __syncwarp. Each chunk's 8 LDG.128/lane for chunk c+1 are issued BEFORE
// computing chunk c: DRAM stays busy under the compute.
// ---------------------------------------------------------------------------
__global__ __launch_bounds__(256)
void vffn_main_kernel(const float* __restrict__ beta,
                      const float* __restrict__ mu,
                      const float* __restrict__ mu_prior,
                      const float* __restrict__ lr_ptr,
                      float* __restrict__ out) {
    __shared__ float Vs[N_ * 20];      // 40 KB, stride-20 conflict-free
    __shared__ float qs[N_];           //  2 KB
    __shared__ float cbuf[2 * 8 * 128];//  8 KB, [buf][warp][128]

    int t = threadIdx.x, lane = t & 31, w = t >> 5, r = lane & 15;
    int b = blockIdx.x >> 6;                 // 64 blocks per batch
    int i0 = (blockIdx.x & 63) << 3;
    int i = i0 + w;                          // this warp's row
    int bn = b * N_ + i;
    float lr = *lr_ptr;

    // This warp's beta row base (head 0); heads at +h*NN
    const float* bw = beta + (size_t)b * H_ * NN + (size_t)i * N_;

    // Issue chunk-0 loads FIRST so DRAM starts before the smem staging.
    float4 hh[8];
    #pragma unroll
    for (int h = 0; h < 8; ++h)
        hh[h] = *(const float4*)(bw + (size_t)h * NN + 4 * lane);

    // Stage V[b] into padded smem (stride 20 floats; float4-aligned)
    const float4* V4 = (const float4*)(g_V + (size_t)b * N_ * K_);
    for (int idx = t; idx < N_ * 4; idx += 256) {
        int j = idx >> 2, q = idx & 3;
        ((float4*)(Vs + j * 20))[q] = V4[idx];
    }
    __syncthreads();
    for (int j = t; j < N_; j += 256) {
        float q = 0.0f;
        #pragma unroll
        for (int k = 0; k < 16; ++k) { float v = Vs[j * 20 + k]; q += v * v; }
        qs[j] = q;
    }
    __syncthreads();

    float vi[16];
    #pragma unroll
    for (int q = 0; q < 4; ++q) {
        float4 v4 = ((const float4*)(Vs + i * 20))[q];
        vi[4*q] = v4.x; vi[4*q+1] = v4.y; vi[4*q+2] = v4.z; vi[4*q+3] = v4.w;
    }
    float qi = qs[i];

    // Commit chunk 0 to buffer 0 (warp-private row)
    *((float4*)(cbuf + (0 * 8 + w) * 128 + 4 * lane)) = head_sum8(hh);
    __syncwarp();

    float S0 = 0.0f, sac = 0.0f;
    float u[32];                          // u[0..15]=Sv, u[16..31]=Tv
    #pragma unroll
    for (int k = 0; k < 32; ++k) u[k] = 0.0f;

    #pragma unroll
    for (int c = 0; c < 4; ++c) {
        // Prefetch chunk c+1 (loads in flight during compute below)
        float4 nh[8];
        if (c < 3) {
            #pragma unroll
            for (int h = 0; h < 8; ++h)
                nh[h] = *(const float4*)(bw + (size_t)h * NN + 128 * (c + 1) + 4 * lane);
        }

        const float* cbrow = cbuf + ((c & 1) * 8 + w) * 128;
        #pragma unroll
        for (int q = 0; q < 4; ++q) {
            int jl = lane + 32 * q;          // lane-stride-1, conflict-free
            int j  = 128 * c + jl;
            float cb = cbrow[jl];

            float vj[16];
            #pragma unroll
            for (int p = 0; p < 4; ++p) {
                float4 uu = ((const float4*)(Vs + j * 20))[p];
                vj[4*p] = uu.x; vj[4*p+1] = uu.y; vj[4*p+2] = uu.z; vj[4*p+3] = uu.w;
            }
            float d0 = 0.0f, d1 = 0.0f;
            #pragma unroll
            for (int k = 0; k < 16; k += 2) { d0 += vi[k]*vj[k]; d1 += vi[k+1]*vj[k+1]; }
            float kl  = 0.5f * (qi + qs[j]) - (d0 + d1);   // / TAU = 1
            float wgt = cb * kl;
            S0  += cb;
            sac += wgt;
            #pragma unroll
            for (int k = 0; k < 16; ++k) {
                u[k]      += cb  * vj[k];
                u[16 + k] += wgt * vj[k];
            }
        }

        if (c < 3) {
            *((float4*)(cbuf + (((c + 1) & 1) * 8 + w) * 128 + 4 * lane)) = head_sum8(nh);
            __syncwarp();
        }
    }

    // ---- recursive-halving reduce-scatter of u[32]: 31 SHFL total.
    {
        bool hi = (lane & 16) != 0;
        #pragma unroll
        for (int k = 0; k < 16; ++k) {
            float send = hi ? u[k] : u[k + 16];
            float keep = hi ? u[k + 16] : u[k];
            u[k] = keep + __shfl_xor_sync(0xffffffffu, send, 16);
        }
        hi = (lane & 8) != 0;
        #pragma unroll
        for (int k = 0; k < 8; ++k) {
            float send = hi ? u[k] : u[k + 8];
            float keep = hi ? u[k + 8] : u[k];
            u[k] = keep + __shfl_xor_sync(0xffffffffu, send, 8);
        }
        hi = (lane & 4) != 0;
        #pragma unroll
        for (int k = 0; k < 4; ++k) {
            float send = hi ? u[k] : u[k + 4];
            float keep = hi ? u[k + 4] : u[k];
            u[k] = keep + __shfl_xor_sync(0xffffffffu, send, 4);
        }
        hi = (lane & 2) != 0;
        #pragma unroll
        for (int k = 0; k < 2; ++k) {
            float send = hi ? u[k] : u[k + 2];
            float keep = hi ? u[k + 2] : u[k];
            u[k] = keep + __shfl_xor_sync(0xffffffffu, send, 2);
        }
        hi = (lane & 1) != 0;
        {
            float send = hi ? u[0] : u[1];
            float keep = hi ? u[1] : u[0];
            u[0] = keep + __shfl_xor_sync(0xffffffffu, send, 1);
        }
    }
    float other = __shfl_xor_sync(0xffffffffu, u[0], 16);
    float Sv_f = (lane < 16) ? u[0] : other;
    float Tv_f = (lane < 16) ? other : u[0];

    #pragma unroll
    for (int off = 16; off > 0; off >>= 1) {
        S0  += __shfl_xor_sync(0xffffffffu, S0,  off);
        sac += __shfl_xor_sync(0xffffffffu, sac, off);
    }

    // rv component r, naturally distributed (lane r holds rv[r])
    float vik = vi[r];
    float rv_own = (S0 * vik - Sv_f)
                 + (sac * (1.0f - S0) * vik + sac * Sv_f - Tv_f);

    // Rotation grad = exp(A) rv
    float Ar[16];
    const float4* A4 = (const float4*)(g_A + (size_t)bn * 256 + r * 16);
    #pragma unroll
    for (int q = 0; q < 4; ++q) {
        float4 a = A4[q];
        Ar[4*q] = a.x; Ar[4*q+1] = a.y; Ar[4*q+2] = a.z; Ar[4*q+3] = a.w;
    }
    float grad = exp_apply<8>(Ar, rv_own);

    if (lane < 16) {
        float m  = mu[bn * 16 + lane];
        float mp = mu_prior[bn * 16 + lane];
        out[bn * 16 + lane] = m - lr * (0.001f * (m - mp) + grad);
    }
}

// ---------------------------------------------------------------------------
extern "C" void kernel_launch(void* const* d_in, const int* in_sizes, int n_in,
                              void* d_out, int out_size) {
    const float* mu       = (const float*)d_in[0];
    const float* beta     = (const float*)d_in[1];
    const float* mu_prior = (const float*)d_in[2];
    const float* phi      = (const float*)d_in[3];
    const float* gen      = (const float*)d_in[4];
    const float* lr       = (const float*)d_in[5];
    float* out = (float*)d_out;

    prep_kernel<<<BN / 8, 256>>>(mu, phi, gen);
    vffn_main_kernel<<<BN / 8, 256>>>(beta, mu, mu_prior, lr, out);
}